// round 3
// baseline (speedup 1.0000x reference)
#include <cuda_runtime.h>
#include <cstdint>

// ---------------- problem constants ----------------
#define BB    8
#define CN    128
#define HN    128
#define WN    128
#define HWN   16384                    // H*W
#define CHWN  (CN*HWN)                 // 2,097,152
#define BCHWN (BB*CHWN)                // 16,777,216
#define NPIX  (BB*HWN)                 // 131,072
#define NSPLIT 16

// ---------------- device scratch (no cudaMalloc allowed) ----------------
__device__ float g_pre [6ull*BCHWN];           // post-1x1-conv, pre-depthwise
__device__ float g_post[6ull*BCHWN];           // post-depthwise
__device__ float g_mean[2*NPIX];
__device__ float g_rstd[2*NPIX];
__device__ float g_Spart[2ull*NSPLIT*BB*CN*CN];
__device__ float g_S   [2ull*BB*CN*CN];        // softmaxed attention
__device__ float g_A   [2ull*BCHWN];           // Aw (att 0), Ai (att 1)
__device__ float g_lin [1ull*BCHWN];           // final linear output (B,HW,128)

// ---------------- f32x2 helpers ----------------
__device__ __forceinline__ unsigned long long ffma2(unsigned long long a,
                                                    unsigned long long b,
                                                    unsigned long long c) {
    asm("fma.rn.f32x2 %0, %1, %2, %0;" : "+l"(c) : "l"(a), "l"(b));
    return c;
}
__device__ __forceinline__ unsigned long long pack2(float lo, float hi) {
    unsigned long long r;
    asm("mov.b64 %0, {%1, %2};" : "=l"(r) : "f"(lo), "f"(hi));
    return r;
}
__device__ __forceinline__ float2 unpack2(unsigned long long v) {
    float2 r;
    asm("mov.b64 {%0, %1}, %2;" : "=f"(r.x), "=f"(r.y) : "l"(v));
    return r;
}

// 32-step micro kernel: acc[4][8] packed pairs over A-rows; B cols = tx + 16*j
template<int APITCH, int BPITCH>
__device__ __forceinline__ void micro32(const float* __restrict__ As,
                                        const float* __restrict__ Bs,
                                        int tx, int ty,
                                        unsigned long long acc[4][8]) {
#pragma unroll 4
    for (int k = 0; k < 32; k++) {
        unsigned long long aa[4];
#pragma unroll
        for (int ii = 0; ii < 4; ii++)
            aa[ii] = *(const unsigned long long*)(As + k*APITCH + ty*8 + 2*ii);
        float bsc[8];
#pragma unroll
        for (int j = 0; j < 8; j++) bsc[j] = Bs[k*BPITCH + tx + 16*j];
#pragma unroll
        for (int j = 0; j < 8; j++) {
            unsigned long long bb = pack2(bsc[j], bsc[j]);
#pragma unroll
            for (int ii = 0; ii < 4; ii++)
                acc[ii][j] = ffma2(aa[ii], bb, acc[ii][j]);
        }
    }
}

// ---------------- kernel 0: LayerNorm stats per pixel ----------------
__global__ __launch_bounds__(256) void k_stats(const float* __restrict__ Fi,
                                               const float* __restrict__ Fw) {
    int inp = blockIdx.y;
    const float* X = inp ? Fw : Fi;
    int p = blockIdx.x * 256 + threadIdx.x;          // [0, NPIX)
    int b = p >> 14, pix = p & (HWN - 1);
    const float* Xb = X + (size_t)b * CHWN + pix;
    float s = 0.f, ss = 0.f;
#pragma unroll 8
    for (int c = 0; c < CN; c++) {
        float v = Xb[(size_t)c * HWN];
        s += v; ss += v * v;
    }
    float m   = s * (1.f / CN);
    float var = ss * (1.f / CN) - m * m;
    g_mean[inp * NPIX + p] = m;
    g_rstd[inp * NPIX + p] = rsqrtf(var + 1e-5f);
}

// ---------------- kernel 1: fused LN + 1x1 conv (GEMM) ----------------
// out[br][b][o][pix] = sum_c W[o][c] * ((x[c,pix]-mu)*rstd*gamma[c]) + bias[o]
__global__ __launch_bounds__(256) void k_ln_c11(
    const float* __restrict__ Fi, const float* __restrict__ Fw,
    const float* __restrict__ g1, const float* __restrict__ g2,
    const float* w0, const float* w1, const float* w2,
    const float* w3, const float* w4, const float* w5,
    const float* b0, const float* b1, const float* b2,
    const float* b3, const float* b4, const float* b5) {
    __shared__ __align__(16) float Ws[32 * 132];     // [kc][o]
    __shared__ __align__(16) float Xs[32 * 128];     // [kc][p] (normalized)
    __shared__ float mu_s[128], rs_s[128];

    int br  = blockIdx.y;
    int inp = (br >= 3);
    const float* X     = inp ? Fw : Fi;
    const float* gamma = inp ? g2 : g1;
    const float* Wsel[6] = {w0, w1, w2, w3, w4, w5};
    const float* Bsel[6] = {b0, b1, b2, b3, b4, b5};
    const float* Wm   = Wsel[br];
    const float* bias = Bsel[br];

    int p0 = blockIdx.x * 128;                       // global pixel
    int b  = p0 >> 14;
    int pix0 = p0 & (HWN - 1);
    const float* Xb = X + (size_t)b * CHWN;

    int tid = threadIdx.x;
    if (tid < 128) {
        mu_s[tid] = g_mean[inp * NPIX + p0 + tid];
        rs_s[tid] = g_rstd[inp * NPIX + p0 + tid];
    }
    __syncthreads();

    int tx = tid & 15, ty = tid >> 4;
    unsigned long long acc[4][8];
#pragma unroll
    for (int ii = 0; ii < 4; ii++)
#pragma unroll
        for (int j = 0; j < 8; j++) acc[ii][j] = 0ull;

    for (int c0 = 0; c0 < CN; c0 += 32) {
#pragma unroll
        for (int t = 0; t < 16; t++) {               // W[o][c0+kc] -> Ws[kc][o]
            int idx = t * 256 + tid;
            int o = idx >> 5, kc = idx & 31;
            Ws[kc * 132 + o] = Wm[o * CN + c0 + kc];
        }
#pragma unroll
        for (int t = 0; t < 16; t++) {               // normalized X tile
            int idx = t * 256 + tid;
            int kc = idx >> 7, dp = idx & 127;
            float v = Xb[(size_t)(c0 + kc) * HWN + pix0 + dp];
            Xs[idx] = (v - mu_s[dp]) * rs_s[dp] * __ldg(&gamma[c0 + kc]);
        }
        __syncthreads();
        micro32<132, 128>(Ws, Xs, tx, ty, acc);
        __syncthreads();
    }

    float* Ob = g_pre + (size_t)br * BCHWN + (size_t)b * CHWN;
#pragma unroll
    for (int ii = 0; ii < 4; ii++) {
        int o0 = ty * 8 + 2 * ii;
        float bo0 = __ldg(&bias[o0]), bo1 = __ldg(&bias[o0 + 1]);
#pragma unroll
        for (int j = 0; j < 8; j++) {
            float2 v = unpack2(acc[ii][j]);
            int p = pix0 + tx + 16 * j;
            Ob[(size_t)o0 * HWN + p]       = v.x + bo0;
            Ob[(size_t)(o0 + 1) * HWN + p] = v.y + bo1;
        }
    }
}

// ---------------- kernel 2: depthwise 3x3, SAME ----------------
__global__ __launch_bounds__(256) void k_dw(
    const float* d0, const float* d1, const float* d2,
    const float* d3, const float* d4, const float* d5,
    const float* e0, const float* e1, const float* e2,
    const float* e3, const float* e4, const float* e5) {
    int br = blockIdx.z, b = blockIdx.y;
    int e = blockIdx.x * 256 + threadIdx.x;          // [0, CHWN)
    int c = e >> 14, pix = e & (HWN - 1);
    int h = pix >> 7, w = pix & 127;
    const float* Wd6[6] = {d0, d1, d2, d3, d4, d5};
    const float* Bd6[6] = {e0, e1, e2, e3, e4, e5};
    const float* Wd = Wd6[br] + c * 9;
    const float* In = g_pre + (size_t)br * BCHWN + (size_t)b * CHWN + (size_t)c * HWN;
    float acc = __ldg(&Bd6[br][c]);
#pragma unroll
    for (int dy = -1; dy <= 1; dy++) {
        int hh = h + dy;
        if ((unsigned)hh < (unsigned)HN) {
            const float* row = In + hh * WN;
#pragma unroll
            for (int dx = -1; dx <= 1; dx++) {
                int ww = w + dx;
                if ((unsigned)ww < (unsigned)WN)
                    acc += __ldg(&Wd[(dy + 1) * 3 + (dx + 1)]) * row[ww];
            }
        }
    }
    g_post[(size_t)br * BCHWN + (size_t)b * CHWN + e] = acc;
}

// ---------------- kernel 3: S = MQ^T * MK, split-K partials ----------------
// MQ, MK: post-dw buffers per batch viewed as row-major (16384, 128)
__global__ __launch_bounds__(256) void k_qk() {
    __shared__ __align__(16) float Qs[32 * 128];
    __shared__ __align__(16) float Ks[32 * 128];
    int s = blockIdx.x, b = blockIdx.y, att = blockIdx.z;
    const float* Q = g_post + (size_t)(att == 0 ? 0 : 3) * BCHWN + (size_t)b * CHWN;
    const float* K = g_post + (size_t)(att == 0 ? 4 : 1) * BCHWN + (size_t)b * CHWN;
    int n0 = s * (HWN / NSPLIT);                     // 1024 rows per split
    int tid = threadIdx.x, tx = tid & 15, ty = tid >> 4;
    unsigned long long acc[4][8];
#pragma unroll
    for (int ii = 0; ii < 4; ii++)
#pragma unroll
        for (int j = 0; j < 8; j++) acc[ii][j] = 0ull;

    for (int nc = 0; nc < (HWN / NSPLIT); nc += 32) {
        size_t base = (size_t)(n0 + nc) * CN;
#pragma unroll
        for (int t = 0; t < 16; t++) {
            int idx = t * 256 + tid;
            Qs[idx] = Q[base + idx];
            Ks[idx] = K[base + idx];
        }
        __syncthreads();
        micro32<128, 128>(Qs, Ks, tx, ty, acc);      // a<-c (Q), b<-d (K)
        __syncthreads();
    }
    float* Sp = g_Spart + ((size_t)(att * NSPLIT + s) * BB + b) * (CN * CN);
#pragma unroll
    for (int ii = 0; ii < 4; ii++) {
        int c0 = ty * 8 + 2 * ii;
#pragma unroll
        for (int j = 0; j < 8; j++) {
            float2 v = unpack2(acc[ii][j]);
            int d = tx + 16 * j;
            Sp[c0 * CN + d]       = v.x;
            Sp[(c0 + 1) * CN + d] = v.y;
        }
    }
}

// ---------------- kernel 4: reduce partials + softmax over d ----------------
__global__ __launch_bounds__(256) void k_softmax() {
    int row  = blockIdx.x * 8 + (threadIdx.x >> 5);  // 2048 rows
    int lane = threadIdx.x & 31;
    int att = row >> 10, rb = row & 1023, b = rb >> 7, c = rb & 127;
    float v[4];
#pragma unroll
    for (int q = 0; q < 4; q++) {
        int d = lane + 32 * q;
        float s = 0.f;
        for (int sp = 0; sp < NSPLIT; sp++)
            s += g_Spart[((size_t)(att * NSPLIT + sp) * BB + b) * (CN * CN) + c * CN + d];
        v[q] = s;
    }
    float mx = fmaxf(fmaxf(v[0], v[1]), fmaxf(v[2], v[3]));
#pragma unroll
    for (int o = 16; o > 0; o >>= 1) mx = fmaxf(mx, __shfl_xor_sync(0xffffffffu, mx, o));
    float e[4], sum = 0.f;
#pragma unroll
    for (int q = 0; q < 4; q++) { e[q] = __expf(v[q] - mx); sum += e[q]; }
#pragma unroll
    for (int o = 16; o > 0; o >>= 1) sum += __shfl_xor_sync(0xffffffffu, sum, o);
    float inv = 1.f / sum;
#pragma unroll
    for (int q = 0; q < 4; q++)
        g_S[(size_t)(att * BB + b) * (CN * CN) + c * CN + lane + 32 * q] = e[q] * inv;
}

// ---------------- kernel 5: A(128x128) @ V(128x16384) ----------------
__global__ __launch_bounds__(256) void k_av() {
    __shared__ __align__(16) float As[32 * 132];     // [d][c] transposed
    __shared__ __align__(16) float Vs[32 * 128];     // [d][n]
    int nt = blockIdx.x, b = blockIdx.y, att = blockIdx.z;
    const float* A = g_S + (size_t)(att * BB + b) * (CN * CN);
    const float* V = g_post + (size_t)(att == 0 ? 5 : 2) * BCHWN + (size_t)b * CHWN;
    float* Out = g_A + (size_t)att * BCHWN + (size_t)b * CHWN;
    int n0 = nt * 128;
    int tid = threadIdx.x, tx = tid & 15, ty = tid >> 4;
    unsigned long long acc[4][8];
#pragma unroll
    for (int ii = 0; ii < 4; ii++)
#pragma unroll
        for (int j = 0; j < 8; j++) acc[ii][j] = 0ull;

    for (int d0 = 0; d0 < CN; d0 += 32) {
#pragma unroll
        for (int t = 0; t < 16; t++) {               // As[kd][c] = A[c][d0+kd]
            int idx = t * 256 + tid;
            int c = idx >> 5, kd = idx & 31;
            As[kd * 132 + c] = A[c * CN + d0 + kd];
        }
#pragma unroll
        for (int t = 0; t < 16; t++) {               // Vs[kd][n]
            int idx = t * 256 + tid;
            int kd = idx >> 7, dn = idx & 127;
            Vs[idx] = V[(size_t)(d0 + kd) * HWN + n0 + dn];
        }
        __syncthreads();
        micro32<132, 128>(As, Vs, tx, ty, acc);      // a<-c, b<-n
        __syncthreads();
    }
#pragma unroll
    for (int ii = 0; ii < 4; ii++) {
        int c0 = ty * 8 + 2 * ii;
#pragma unroll
        for (int j = 0; j < 8; j++) {
            float2 v = unpack2(acc[ii][j]);
            int n = n0 + tx + 16 * j;
            Out[(size_t)c0 * HWN + n]       = v.x;
            Out[(size_t)(c0 + 1) * HWN + n] = v.y;
        }
    }
}

// ---------------- kernel 6: final linear (16384x256)@(256x128) per batch ----
// cat rows are contiguous 128-float slices of g_A buffers (raw reshape!)
__global__ __launch_bounds__(256) void k_final(const float* __restrict__ lw,
                                               const float* __restrict__ lb) {
    __shared__ __align__(16) float As[32 * 132];     // [t][n] transposed
    __shared__ __align__(16) float Ls[32 * 132];     // [t][co] transposed
    int nt = blockIdx.x, b = blockIdx.y;
    int n0 = nt * 128;
    int tid = threadIdx.x, tx = tid & 15, ty = tid >> 4;
    unsigned long long acc[4][8];
#pragma unroll
    for (int ii = 0; ii < 4; ii++)
#pragma unroll
        for (int j = 0; j < 8; j++) acc[ii][j] = 0ull;

    for (int part = 0; part < 2; part++) {
        const float* A = g_A + (size_t)(part * BB + b) * CHWN;  // (16384,128) rows
        int off = part * 128;
        for (int t0 = 0; t0 < 128; t0 += 32) {
#pragma unroll
            for (int t = 0; t < 16; t++) {           // As[kt][n] = A[n0+n][t0+kt]
                int idx = t * 256 + tid;
                int n = idx >> 5, kt = idx & 31;
                As[kt * 132 + n] = A[(size_t)(n0 + n) * CN + t0 + kt];
            }
#pragma unroll
            for (int t = 0; t < 16; t++) {           // Ls[kt][co] = lw[co][off+t0+kt]
                int idx = t * 256 + tid;
                int co = idx >> 5, kt = idx & 31;
                Ls[kt * 132 + co] = lw[co * 256 + off + t0 + kt];
            }
            __syncthreads();
            micro32<132, 132>(As, Ls, tx, ty, acc);  // a<-n, b<-co
            __syncthreads();
        }
    }
    float* Ob = g_lin + (size_t)b * CHWN;
#pragma unroll
    for (int ii = 0; ii < 4; ii++) {
        int nr0 = n0 + ty * 8 + 2 * ii;
#pragma unroll
        for (int j = 0; j < 8; j++) {
            float2 v = unpack2(acc[ii][j]);
            int co = tx + 16 * j;
            float bi = __ldg(&lb[co]);
            Ob[(size_t)nr0 * CN + co]       = v.x + bi;
            Ob[(size_t)(nr0 + 1) * CN + co] = v.y + bi;
        }
    }
}

// ---------------- kernel 7: tail transpose (128x16384 -> 16384x128) + residual
// final.flat[b][r*128+cc] = g_lin.flat[b][cc*16384+r] + Fi + Fw
__global__ __launch_bounds__(256) void k_tail(const float* __restrict__ Fi,
                                              const float* __restrict__ Fw,
                                              float* __restrict__ out) {
    __shared__ float tile[32][33];
    int b  = blockIdx.z;
    int r0 = blockIdx.x * 32;                        // 512 tiles
    int c0 = blockIdx.y * 32;                        // 4 tiles
    const float* In = g_lin + (size_t)b * CHWN;
    int tx = threadIdx.x & 31, ty = threadIdx.x >> 5;
#pragma unroll
    for (int s2 = 0; s2 < 4; s2++) {
        int cc = c0 + ty + 8 * s2;
        tile[ty + 8 * s2][tx] = In[(size_t)cc * HWN + r0 + tx];
    }
    __syncthreads();
    size_t base = (size_t)b * CHWN;
#pragma unroll
    for (int s2 = 0; s2 < 4; s2++) {
        int r = r0 + ty + 8 * s2;
        size_t idx = base + (size_t)r * CN + c0 + tx;
        out[idx] = tile[tx][ty + 8 * s2] + Fi[idx] + Fw[idx];
    }
}

// ---------------- launch ----------------
extern "C" void kernel_launch(void* const* d_in, const int* in_sizes, int n_in,
                              void* d_out, int out_size) {
    const float* Fi = (const float*)d_in[0];
    const float* Fw = (const float*)d_in[1];
    const float* g1 = (const float*)d_in[2];
    const float* g2 = (const float*)d_in[3];

    const float *qw1, *kw1, *vw1, *qw2, *kw2, *vw2;
    const float *qb1, *kb1, *vb1, *qb2, *kb2, *vb2;
    const float *qdw1, *kdw1, *vdw1, *qdw2, *kdw2, *vdw2;
    const float *qdb1, *kdb1, *vdb1, *qdb2, *kdb2, *vdb2;
    const float *lw, *lb;

    if (in_sizes[5] == CN) {
        // signature order: qw1, qb1, kw1, kb1, vw1, vb1, qw2, qb2, ...
        qw1 = (const float*)d_in[4];  qb1 = (const float*)d_in[5];
        kw1 = (const float*)d_in[6];  kb1 = (const float*)d_in[7];
        vw1 = (const float*)d_in[8];  vb1 = (const float*)d_in[9];
        qw2 = (const float*)d_in[10]; qb2 = (const float*)d_in[11];
        kw2 = (const float*)d_in[12]; kb2 = (const float*)d_in[13];
        vw2 = (const float*)d_in[14]; vb2 = (const float*)d_in[15];
        qdw1 = (const float*)d_in[16]; qdb1 = (const float*)d_in[17];
        kdw1 = (const float*)d_in[18]; kdb1 = (const float*)d_in[19];
        vdw1 = (const float*)d_in[20]; vdb1 = (const float*)d_in[21];
        qdw2 = (const float*)d_in[22]; qdb2 = (const float*)d_in[23];
        kdw2 = (const float*)d_in[24]; kdb2 = (const float*)d_in[25];
        vdw2 = (const float*)d_in[26]; vdb2 = (const float*)d_in[27];
    } else {
        // setup_inputs() dict insertion order:
        // qw1,kw1,vw1,qw2,kw2,vw2 | qb1,kb1,vb1,qb2,kb2,vb2 |
        // qdw1,kdw1,vdw1,qdw2,kdw2,vdw2 | qdb1,kdb1,vdb1,qdb2,kdb2,vdb2
        qw1 = (const float*)d_in[4];  kw1 = (const float*)d_in[5];
        vw1 = (const float*)d_in[6];  qw2 = (const float*)d_in[7];
        kw2 = (const float*)d_in[8];  vw2 = (const float*)d_in[9];
        qb1 = (const float*)d_in[10]; kb1 = (const float*)d_in[11];
        vb1 = (const float*)d_in[12]; qb2 = (const float*)d_in[13];
        kb2 = (const float*)d_in[14]; vb2 = (const float*)d_in[15];
        qdw1 = (const float*)d_in[16]; kdw1 = (const float*)d_in[17];
        vdw1 = (const float*)d_in[18]; qdw2 = (const float*)d_in[19];
        kdw2 = (const float*)d_in[20]; vdw2 = (const float*)d_in[21];
        qdb1 = (const float*)d_in[22]; kdb1 = (const float*)d_in[23];
        vdb1 = (const float*)d_in[24]; qdb2 = (const float*)d_in[25];
        kdb2 = (const float*)d_in[26]; vdb2 = (const float*)d_in[27];
    }
    lw = (const float*)d_in[28];
    lb = (const float*)d_in[29];
    float* out = (float*)d_out;

    k_stats  <<<dim3(NPIX / 256, 2), 256>>>(Fi, Fw);
    k_ln_c11 <<<dim3(NPIX / 128, 6), 256>>>(Fi, Fw, g1, g2,
                                            qw1, kw1, vw1, qw2, kw2, vw2,
                                            qb1, kb1, vb1, qb2, kb2, vb2);
    k_dw     <<<dim3(CHWN / 256, BB, 6), 256>>>(qdw1, kdw1, vdw1, qdw2, kdw2, vdw2,
                                                qdb1, kdb1, vdb1, qdb2, kdb2, vdb2);
    k_qk     <<<dim3(NSPLIT, BB, 2), 256>>>();
    k_softmax<<<dim3(256), 256>>>();
    k_av     <<<dim3(HWN / 128, BB, 2), 256>>>();
    k_final  <<<dim3(HWN / 128, BB), 256>>>(lw, lb);
    k_tail   <<<dim3(HWN / 32, CN / 32, BB), 256>>>(Fi, Fw, out);
}